// round 6
// baseline (speedup 1.0000x reference)
#include <cuda_runtime.h>
#include <cuda_fp16.h>
#include <cstdint>

#define NNODES 100000
#define NEDGES 1600000
#define DIN    64
#define DH     128
#define NG     64
#define NEMB   64
#define SCANB  1024
#define NBLK   ((NNODES + SCANB - 1) / SCANB)   // 98

typedef unsigned long long ull;

// ---------------- scratch (static device memory; no allocation) ----------------
__device__ float  g_agg[(size_t)NNODES * DH];
__device__ float  g_h1 [(size_t)NNODES * DH];
__device__ float  g_h2 [(size_t)NNODES * DH];
__device__ __half g_xh [(size_t)NNODES * DIN];   // fp16 shadow of x
__device__ __half g_hh [(size_t)NNODES * DH];    // fp16 shadow of current h
__device__ int    g_deg_i[NNODES];
__device__ int    g_off[NNODES + 1];
__device__ int    g_cursor[NNODES];
__device__ int    g_part[NBLK];
__device__ int    g_csrc[NEDGES];
__device__ float  g_pooled[NG * DH];

// ---------------- CSR build ----------------
__global__ void zero_deg_kernel() {
    int i = blockIdx.x * blockDim.x + threadIdx.x;
    if (i < NNODES) g_deg_i[i] = 0;
}
__global__ void hist_kernel(const int* __restrict__ dst) {
    int e = blockIdx.x * blockDim.x + threadIdx.x;
    if (e < NEDGES) atomicAdd(&g_deg_i[dst[e]], 1);
}
__global__ __launch_bounds__(SCANB) void scan_block_kernel() {
    __shared__ int sh[SCANB];
    int i = blockIdx.x * SCANB + threadIdx.x;
    int v = (i < NNODES) ? g_deg_i[i] : 0;
    int x = v;
    sh[threadIdx.x] = x;
    __syncthreads();
#pragma unroll
    for (int d = 1; d < SCANB; d <<= 1) {
        int t = (threadIdx.x >= d) ? sh[threadIdx.x - d] : 0;
        __syncthreads();
        x += t;
        sh[threadIdx.x] = x;
        __syncthreads();
    }
    if (i < NNODES) g_off[i] = x - v;
    if (threadIdx.x == SCANB - 1) g_part[blockIdx.x] = x;
}
__global__ __launch_bounds__(128) void scan_part_kernel() {
    __shared__ int sh[128];
    int t = threadIdx.x;
    int v = (t < NBLK) ? g_part[t] : 0;
    int x = v;
    sh[t] = x;
    __syncthreads();
#pragma unroll
    for (int d = 1; d < 128; d <<= 1) {
        int u = (t >= d) ? sh[t - d] : 0;
        __syncthreads();
        x += u;
        sh[t] = x;
        __syncthreads();
    }
    if (t < NBLK) g_part[t] = x - v;
}
__global__ void scan_add_kernel() {
    int i = blockIdx.x * blockDim.x + threadIdx.x;
    if (i < NNODES) {
        int o = g_off[i] + g_part[i >> 10];
        g_off[i] = o;
        g_cursor[i] = o;
    }
    if (i == 0) g_off[NNODES] = NEDGES;
}
__global__ void fill_kernel(const int* __restrict__ src, const int* __restrict__ dst) {
    int e = blockIdx.x * blockDim.x + threadIdx.x;
    if (e < NEDGES) {
        int t = dst[e];
        int slot = atomicAdd(&g_cursor[t], 1);
        g_csrc[slot] = src[e];
    }
}

// ---------------- x -> fp16 shadow ----------------
__global__ void x2h_kernel(const float* __restrict__ x) {
    int i = blockIdx.x * blockDim.x + threadIdx.x;   // half2 index
    int total = NNODES * (DIN / 2);
    if (i < total) {
        float2 v = ((const float2*)x)[i];
        ((__half2*)g_xh)[i] = __float22half2_rn(v);
    }
}

// ---------------- atomic-free mean aggregation from fp16 shadow ----------------
// d=128: row = 256B; lane owns one uint2 (4 halves)
__global__ __launch_bounds__(256) void agg128h_kernel() {
    int wid = (blockIdx.x * blockDim.x + threadIdx.x) >> 5;
    int lane = threadIdx.x & 31;
    if (wid >= NNODES) return;
    int s = g_off[wid], e = g_off[wid + 1];
    float ax = 0.f, ay = 0.f, az = 0.f, aw = 0.f;
    const uint2* fh = (const uint2*)g_hh;
    int i = s;
    for (; i + 4 <= e; i += 4) {
        int n0 = g_csrc[i], n1 = g_csrc[i + 1], n2 = g_csrc[i + 2], n3 = g_csrc[i + 3];
        uint2 u0 = fh[(size_t)n0 * 32 + lane];
        uint2 u1 = fh[(size_t)n1 * 32 + lane];
        uint2 u2 = fh[(size_t)n2 * 32 + lane];
        uint2 u3 = fh[(size_t)n3 * 32 + lane];
        float2 p;
        p = __half22float2(*(__half2*)&u0.x); ax += p.x; ay += p.y;
        p = __half22float2(*(__half2*)&u0.y); az += p.x; aw += p.y;
        p = __half22float2(*(__half2*)&u1.x); ax += p.x; ay += p.y;
        p = __half22float2(*(__half2*)&u1.y); az += p.x; aw += p.y;
        p = __half22float2(*(__half2*)&u2.x); ax += p.x; ay += p.y;
        p = __half22float2(*(__half2*)&u2.y); az += p.x; aw += p.y;
        p = __half22float2(*(__half2*)&u3.x); ax += p.x; ay += p.y;
        p = __half22float2(*(__half2*)&u3.y); az += p.x; aw += p.y;
    }
    for (; i < e; i++) {
        int nb = g_csrc[i];
        uint2 u = fh[(size_t)nb * 32 + lane];
        float2 p;
        p = __half22float2(*(__half2*)&u.x); ax += p.x; ay += p.y;
        p = __half22float2(*(__half2*)&u.y); az += p.x; aw += p.y;
    }
    float inv = 1.0f / (float)max(e - s, 1);
    float4 o = make_float4(ax * inv, ay * inv, az * inv, aw * inv);
    ((float4*)g_agg)[(size_t)wid * 32 + lane] = o;
}
// d=64: row = 128B; lane owns one half2
__global__ __launch_bounds__(256) void agg64h_kernel() {
    int wid = (blockIdx.x * blockDim.x + threadIdx.x) >> 5;
    int lane = threadIdx.x & 31;
    if (wid >= NNODES) return;
    int s = g_off[wid], e = g_off[wid + 1];
    float ax = 0.f, ay = 0.f;
    const __half2* fh = (const __half2*)g_xh;
    int i = s;
    for (; i + 4 <= e; i += 4) {
        int n0 = g_csrc[i], n1 = g_csrc[i + 1], n2 = g_csrc[i + 2], n3 = g_csrc[i + 3];
        float2 p0 = __half22float2(fh[(size_t)n0 * 32 + lane]);
        float2 p1 = __half22float2(fh[(size_t)n1 * 32 + lane]);
        float2 p2 = __half22float2(fh[(size_t)n2 * 32 + lane]);
        float2 p3 = __half22float2(fh[(size_t)n3 * 32 + lane]);
        ax += p0.x + p1.x + p2.x + p3.x;
        ay += p0.y + p1.y + p2.y + p3.y;
    }
    for (; i < e; i++) {
        int nb = g_csrc[i];
        float2 p = __half22float2(fh[(size_t)nb * 32 + lane]);
        ax += p.x; ay += p.y;
    }
    float inv = 1.0f / (float)max(e - s, 1);
    ((float2*)g_agg)[(size_t)wid * 32 + lane] = make_float2(ax * inv, ay * inv);
}

// ---------------- fused SAGE GEMM (packed f32x2 FMA) + fp16 shadow write ----------------
#define BM 128
#define BN 128
#define BK 16

__device__ __forceinline__ void ffma2(ull& acc, ull a2, ull w2) {
    asm("fma.rn.f32x2 %0, %1, %2, %0;" : "+l"(acc) : "l"(a2), "l"(w2));
}
__device__ __forceinline__ ull pack2(float a) {
    ull r;
    asm("mov.b64 %0, {%1, %1};" : "=l"(r) : "r"(__float_as_uint(a)));
    return r;
}

__global__ __launch_bounds__(256) void sage_gemm(
    const float* __restrict__ agg, const float* __restrict__ xin,
    const float* __restrict__ Wl, const float* __restrict__ Wr,
    const float* __restrict__ bias, float* __restrict__ out,
    __half* __restrict__ outh,               // optional fp16 shadow (may be null)
    int Nn, int K)
{
    __shared__ float As[BK][BM + 4];
    __shared__ float Ws[BK][BN];

    int tid = threadIdx.x;
    int block_m = blockIdx.x * BM;
    int tm = tid >> 4;
    int tn = tid & 15;

    int la_m   = tid >> 1;
    int la_kkb = (tid & 1) * 8;
    int lw_kk  = tid >> 4;
    int lw_n   = (tid & 15) * 8;

    ull acc2[8][4];
#pragma unroll
    for (int i = 0; i < 8; i++)
#pragma unroll
        for (int j = 0; j < 4; j++) acc2[i][j] = 0ull;

    int Ktot = 2 * K;
    for (int k0 = 0; k0 < Ktot; k0 += BK) {
        {
            int row = block_m + la_m;
            float4 v0 = make_float4(0.f, 0.f, 0.f, 0.f), v1 = v0;
            if (row < Nn) {
                int k = k0 + la_kkb;
                const float* base = (k < K) ? (agg + (size_t)row * K + k)
                                            : (xin + (size_t)row * K + (k - K));
                v0 = ((const float4*)base)[0];
                v1 = ((const float4*)base)[1];
            }
            As[la_kkb + 0][la_m] = v0.x;
            As[la_kkb + 1][la_m] = v0.y;
            As[la_kkb + 2][la_m] = v0.z;
            As[la_kkb + 3][la_m] = v0.w;
            As[la_kkb + 4][la_m] = v1.x;
            As[la_kkb + 5][la_m] = v1.y;
            As[la_kkb + 6][la_m] = v1.z;
            As[la_kkb + 7][la_m] = v1.w;
        }
        {
            int k = k0 + lw_kk;
            const float* wb = (k < K) ? (Wl + (size_t)k * BN + lw_n)
                                      : (Wr + (size_t)(k - K) * BN + lw_n);
            float4 w0 = ((const float4*)wb)[0];
            float4 w1 = ((const float4*)wb)[1];
            ((float4*)&Ws[lw_kk][lw_n])[0] = w0;
            ((float4*)&Ws[lw_kk][lw_n])[1] = w1;
        }
        __syncthreads();

#pragma unroll
        for (int kk = 0; kk < BK; kk++) {
            float4 a0 = ((const float4*)&As[kk][tm * 8])[0];
            float4 a1 = ((const float4*)&As[kk][tm * 8])[1];
            float4 w0 = ((const float4*)&Ws[kk][tn * 8])[0];
            float4 w1 = ((const float4*)&Ws[kk][tn * 8])[1];
            ull w2[4];
            w2[0] = ((ull*)&w0)[0];
            w2[1] = ((ull*)&w0)[1];
            w2[2] = ((ull*)&w1)[0];
            w2[3] = ((ull*)&w1)[1];
            float a[8];
            a[0]=a0.x; a[1]=a0.y; a[2]=a0.z; a[3]=a0.w;
            a[4]=a1.x; a[5]=a1.y; a[6]=a1.z; a[7]=a1.w;
#pragma unroll
            for (int i = 0; i < 8; i++) {
                ull a2 = pack2(a[i]);
#pragma unroll
                for (int j = 0; j < 4; j++)
                    ffma2(acc2[i][j], a2, w2[j]);
            }
        }
        __syncthreads();
    }

#pragma unroll
    for (int i = 0; i < 8; i++) {
        int row = block_m + tm * 8 + i;
        if (row < Nn) {
#pragma unroll
            for (int j = 0; j < 8; j += 4) {
                int n = tn * 8 + j;
                float2 p0 = *(float2*)&acc2[i][j / 2];
                float2 p1 = *(float2*)&acc2[i][j / 2 + 1];
                float4 r;
                r.x = fmaxf(p0.x + bias[n + 0], 0.f);
                r.y = fmaxf(p0.y + bias[n + 1], 0.f);
                r.z = fmaxf(p1.x + bias[n + 2], 0.f);
                r.w = fmaxf(p1.y + bias[n + 3], 0.f);
                *((float4*)&out[(size_t)row * BN + n]) = r;
                if (outh) {
                    __half2 h0 = __float22half2_rn(make_float2(r.x, r.y));
                    __half2 h1 = __float22half2_rn(make_float2(r.z, r.w));
                    uint2 u;
                    u.x = *(uint32_t*)&h0;
                    u.y = *(uint32_t*)&h1;
                    *(uint2*)&outh[(size_t)row * BN + n] = u;
                }
            }
        }
    }
}

// ---------------- pooling: block per graph, batch is sorted ----------------
__device__ __forceinline__ int lower_bound_batch(const int* batch, int key) {
    int lo = 0, hi = NNODES;
    while (lo < hi) {
        int mid = (lo + hi) >> 1;
        if (batch[mid] < key) lo = mid + 1; else hi = mid;
    }
    return lo;
}
__global__ __launch_bounds__(DH) void pool_kernel(const int* __restrict__ batch,
                                                  const float* __restrict__ h) {
    __shared__ int s_start, s_end;
    int g = blockIdx.x;
    if (threadIdx.x == 0) s_start = lower_bound_batch(batch, g);
    if (threadIdx.x == 1) s_end   = lower_bound_batch(batch, g + 1);
    __syncthreads();
    int start = s_start, end = s_end;
    float acc = 0.f;
    int col = threadIdx.x;
#pragma unroll 4
    for (int n = start; n < end; n++)
        acc += h[(size_t)n * DH + col];
    g_pooled[g * DH + col] = acc / (float)max(end - start, 1);
}

// ---------------- final MLP ----------------
__global__ __launch_bounds__(NEMB) void mlp_kernel(
    const float* __restrict__ W1, const float* __restrict__ bl1,
    const float* __restrict__ W2, const float* __restrict__ bl2,
    float* __restrict__ out)
{
    __shared__ float p[DH];
    __shared__ float hid[NEMB];
    int g = blockIdx.x;
    int t = threadIdx.x;
    p[t]      = g_pooled[g * DH + t];
    p[t + 64] = g_pooled[g * DH + 64 + t];
    __syncthreads();
    float s = bl1[t];
#pragma unroll 8
    for (int k = 0; k < DH; k++) s += p[k] * W1[k * NEMB + t];
    hid[t] = fmaxf(s, 0.f);
    __syncthreads();
    float o = bl2[t];
#pragma unroll 8
    for (int j = 0; j < NEMB; j++) o += hid[j] * W2[j * NEMB + t];
    out[g * NEMB + t] = o;
}

// ---------------- launch ----------------
extern "C" void kernel_launch(void* const* d_in, const int* in_sizes, int n_in,
                              void* d_out, int out_size) {
    const float* x     = (const float*)d_in[0];
    const int*   ei    = (const int*)d_in[1];      // int32 (JAX x64 disabled)
    const int*   src   = ei;
    const int*   dst   = ei + NEDGES;
    const int*   batch = (const int*)d_in[2];
    const float *Wl1 = (const float*)d_in[3],  *Wr1 = (const float*)d_in[4],  *b1 = (const float*)d_in[5];
    const float *Wl2 = (const float*)d_in[6],  *Wr2 = (const float*)d_in[7],  *b2 = (const float*)d_in[8];
    const float *Wl3 = (const float*)d_in[9],  *Wr3 = (const float*)d_in[10], *b3 = (const float*)d_in[11];
    const float *W1  = (const float*)d_in[12], *bl1 = (const float*)d_in[13];
    const float *W2  = (const float*)d_in[14], *bl2 = (const float*)d_in[15];

    float* agg;  cudaGetSymbolAddress((void**)&agg, g_agg);
    float* h1;   cudaGetSymbolAddress((void**)&h1,  g_h1);
    float* h2;   cudaGetSymbolAddress((void**)&h2,  g_h2);
    __half* hh;  cudaGetSymbolAddress((void**)&hh,  g_hh);

    const int T = 256;
    int gemm_blocks = (NNODES + BM - 1) / BM;
    int warp_blocks = (NNODES * 32 + T - 1) / T;

    // ---- CSR build ----
    zero_deg_kernel<<<(NNODES + T - 1) / T, T>>>();
    hist_kernel<<<(NEDGES + T - 1) / T, T>>>(dst);
    scan_block_kernel<<<NBLK, SCANB>>>();
    scan_part_kernel<<<1, 128>>>();
    scan_add_kernel<<<(NNODES + T - 1) / T, T>>>();
    fill_kernel<<<(NEDGES + T - 1) / T, T>>>(src, dst);

    // ---- fp16 shadow of x ----
    x2h_kernel<<<(NNODES * (DIN / 2) + T - 1) / T, T>>>(x);

    // ---- layer 1 (d=64): agg from x_h, GEMM writes h1 + hh(fp16) ----
    agg64h_kernel<<<warp_blocks, T>>>();
    sage_gemm<<<gemm_blocks, 256>>>(agg, x, Wl1, Wr1, b1, h1, hh, NNODES, DIN);

    // ---- layer 2 (d=128): agg from hh, GEMM writes h2 + hh ----
    agg128h_kernel<<<warp_blocks, T>>>();
    sage_gemm<<<gemm_blocks, 256>>>(agg, h1, Wl2, Wr2, b2, h2, hh, NNODES, DH);

    // ---- layer 3: agg from hh, GEMM writes h1 (no shadow needed) ----
    agg128h_kernel<<<warp_blocks, T>>>();
    sage_gemm<<<gemm_blocks, 256>>>(agg, h2, Wl3, Wr3, b3, h1, (__half*)nullptr, NNODES, DH);

    // ---- pool + MLP ----
    pool_kernel<<<NG, DH>>>(batch, h1);
    mlp_kernel<<<NG, NEMB>>>(W1, bl1, W2, bl2, (float*)d_out);
}

// round 7
// speedup vs baseline: 1.3543x; 1.3543x over previous
#include <cuda_runtime.h>
#include <cuda_fp16.h>
#include <cstdint>

#define NNODES 100000
#define NEDGES 1600000
#define DIN    64
#define DH     128
#define NG     64
#define NEMB   64
#define SCANB  1024
#define NBLK   ((NNODES + SCANB - 1) / SCANB)   // 98
#define ASTRIDE 256                              // fp16 operand row stride (halves)
#define NTILES ((NNODES + 127) / 128)            // 782

// ---------------- scratch (static device memory; no allocation) ----------------
__device__ float  g_h[(size_t)NNODES * DH];                    // current layer output (fp32)
__device__ __align__(16) __half g_Ahi[(size_t)NNODES * ASTRIDE];
__device__ __align__(16) __half g_Alo[(size_t)NNODES * ASTRIDE];
__device__ __align__(16) __half g_W1h[128 * ASTRIDE], g_W1l[128 * ASTRIDE];  // Wt[n][k]
__device__ __align__(16) __half g_W2h[128 * ASTRIDE], g_W2l[128 * ASTRIDE];
__device__ __align__(16) __half g_W3h[128 * ASTRIDE], g_W3l[128 * ASTRIDE];
__device__ int    g_deg_i[NNODES];
__device__ int    g_off[NNODES + 1];
__device__ int    g_cursor[NNODES];
__device__ int    g_part[NBLK];
__device__ int    g_csrc[NEDGES];
__device__ float  g_pooled[NG * DH];

// ---------------- CSR build ----------------
__global__ void zero_deg_kernel() {
    int i = blockIdx.x * blockDim.x + threadIdx.x;
    if (i < NNODES) g_deg_i[i] = 0;
}
__global__ void hist_kernel(const int* __restrict__ dst) {
    int e = blockIdx.x * blockDim.x + threadIdx.x;
    if (e < NEDGES) atomicAdd(&g_deg_i[dst[e]], 1);
}
__global__ __launch_bounds__(SCANB) void scan_block_kernel() {
    __shared__ int sh[SCANB];
    int i = blockIdx.x * SCANB + threadIdx.x;
    int v = (i < NNODES) ? g_deg_i[i] : 0;
    int x = v;
    sh[threadIdx.x] = x;
    __syncthreads();
#pragma unroll
    for (int d = 1; d < SCANB; d <<= 1) {
        int t = (threadIdx.x >= d) ? sh[threadIdx.x - d] : 0;
        __syncthreads();
        x += t;
        sh[threadIdx.x] = x;
        __syncthreads();
    }
    if (i < NNODES) g_off[i] = x - v;
    if (threadIdx.x == SCANB - 1) g_part[blockIdx.x] = x;
}
__global__ __launch_bounds__(128) void scan_part_kernel() {
    __shared__ int sh[128];
    int t = threadIdx.x;
    int v = (t < NBLK) ? g_part[t] : 0;
    int x = v;
    sh[t] = x;
    __syncthreads();
#pragma unroll
    for (int d = 1; d < 128; d <<= 1) {
        int u = (t >= d) ? sh[t - d] : 0;
        __syncthreads();
        x += u;
        sh[t] = x;
        __syncthreads();
    }
    if (t < NBLK) g_part[t] = x - v;
}
__global__ void scan_add_kernel() {
    int i = blockIdx.x * blockDim.x + threadIdx.x;
    if (i < NNODES) {
        int o = g_off[i] + g_part[i >> 10];
        g_off[i] = o;
        g_cursor[i] = o;
    }
    if (i == 0) g_off[NNODES] = NEDGES;
}
__global__ void fill_kernel(const int* __restrict__ src, const int* __restrict__ dst) {
    int e = blockIdx.x * blockDim.x + threadIdx.x;
    if (e < NEDGES) {
        int t = dst[e];
        int slot = atomicAdd(&g_cursor[t], 1);
        g_csrc[slot] = src[e];
    }
}

// ---------------- helpers: fp32 -> fp16 hi/lo ----------------
__device__ __forceinline__ void split2(float a, float b, __half2& hi, __half2& lo) {
    __half ha = __float2half_rn(a), hb = __float2half_rn(b);
    hi = __halves2half2(ha, hb);
    lo = __halves2half2(__float2half_rn(a - __half2float(ha)),
                        __float2half_rn(b - __half2float(hb)));
}

// ---------------- x -> fp16 hi/lo self-half (layer1 cols 64..127) ----------------
__global__ void x2h_kernel(const float* __restrict__ x) {
    int i = blockIdx.x * blockDim.x + threadIdx.x;   // half2 index within x
    int total = NNODES * (DIN / 2);
    if (i >= total) return;
    int n = i >> 5, cp = i & 31;                     // 32 half2 per row
    float2 v = ((const float2*)x)[(size_t)n * 32 + cp];
    __half2 hi, lo;
    split2(v.x, v.y, hi, lo);
    *(__half2*)&g_Ahi[(size_t)n * ASTRIDE + 64 + cp * 2] = hi;
    *(__half2*)&g_Alo[(size_t)n * ASTRIDE + 64 + cp * 2] = lo;
}

// ---------------- aggregation: mean of neighbor rows -> fp16 hi/lo into A cols [0,K) ----------------
__global__ __launch_bounds__(256) void agg64_kernel(const float* __restrict__ feat) {
    int wid = (blockIdx.x * blockDim.x + threadIdx.x) >> 5;
    int lane = threadIdx.x & 31;
    if (wid >= NNODES) return;
    int s = g_off[wid], e = g_off[wid + 1];
    float ax = 0.f, ay = 0.f;
    const float2* f2 = (const float2*)feat;
    int i = s;
    for (; i + 4 <= e; i += 4) {
        int n0 = g_csrc[i], n1 = g_csrc[i+1], n2 = g_csrc[i+2], n3 = g_csrc[i+3];
        float2 v0 = f2[(size_t)n0 * 32 + lane];
        float2 v1 = f2[(size_t)n1 * 32 + lane];
        float2 v2 = f2[(size_t)n2 * 32 + lane];
        float2 v3 = f2[(size_t)n3 * 32 + lane];
        ax += v0.x + v1.x + v2.x + v3.x;
        ay += v0.y + v1.y + v2.y + v3.y;
    }
    for (; i < e; i++) {
        int nb = g_csrc[i];
        float2 v = f2[(size_t)nb * 32 + lane];
        ax += v.x; ay += v.y;
    }
    float inv = 1.0f / (float)max(e - s, 1);
    __half2 hi, lo;
    split2(ax * inv, ay * inv, hi, lo);
    *(__half2*)&g_Ahi[(size_t)wid * ASTRIDE + lane * 2] = hi;
    *(__half2*)&g_Alo[(size_t)wid * ASTRIDE + lane * 2] = lo;
}
__global__ __launch_bounds__(256) void agg128_kernel(const float* __restrict__ feat) {
    int wid = (blockIdx.x * blockDim.x + threadIdx.x) >> 5;
    int lane = threadIdx.x & 31;
    if (wid >= NNODES) return;
    int s = g_off[wid], e = g_off[wid + 1];
    float4 acc = make_float4(0.f, 0.f, 0.f, 0.f);
    const float4* f4 = (const float4*)feat;
    int i = s;
    for (; i + 4 <= e; i += 4) {
        int n0 = g_csrc[i], n1 = g_csrc[i+1], n2 = g_csrc[i+2], n3 = g_csrc[i+3];
        float4 v0 = f4[(size_t)n0 * 32 + lane];
        float4 v1 = f4[(size_t)n1 * 32 + lane];
        float4 v2 = f4[(size_t)n2 * 32 + lane];
        float4 v3 = f4[(size_t)n3 * 32 + lane];
        acc.x += v0.x + v1.x + v2.x + v3.x;
        acc.y += v0.y + v1.y + v2.y + v3.y;
        acc.z += v0.z + v1.z + v2.z + v3.z;
        acc.w += v0.w + v1.w + v2.w + v3.w;
    }
    for (; i < e; i++) {
        int nb = g_csrc[i];
        float4 v = f4[(size_t)nb * 32 + lane];
        acc.x += v.x; acc.y += v.y; acc.z += v.z; acc.w += v.w;
    }
    float inv = 1.0f / (float)max(e - s, 1);
    __half2 h0, l0, h1, l1;
    split2(acc.x * inv, acc.y * inv, h0, l0);
    split2(acc.z * inv, acc.w * inv, h1, l1);
    uint2 uh, ul;
    uh.x = *(uint32_t*)&h0; uh.y = *(uint32_t*)&h1;
    ul.x = *(uint32_t*)&l0; ul.y = *(uint32_t*)&l1;
    *(uint2*)&g_Ahi[(size_t)wid * ASTRIDE + lane * 4] = uh;
    *(uint2*)&g_Alo[(size_t)wid * ASTRIDE + lane * 4] = ul;
}

// ---------------- weight prep: Wt[n][k] fp16 hi/lo, k = [Wl ; Wr] ----------------
__global__ void prep_w(const float* __restrict__ Wl, const float* __restrict__ Wr, int K,
                       __half* __restrict__ wh, __half* __restrict__ wl) {
    int idx = blockIdx.x * blockDim.x + threadIdx.x;
    int Ktot = 2 * K;
    if (idx >= 128 * Ktot) return;
    int n = idx / Ktot, k = idx % Ktot;
    float w = (k < K) ? Wl[k * 128 + n] : Wr[(k - K) * 128 + n];
    __half hi = __float2half_rn(w);
    wh[(size_t)n * ASTRIDE + k] = hi;
    wl[(size_t)n * ASTRIDE + k] = __float2half_rn(w - __half2float(hi));
}

// ---------------- HMMA GEMM: out[128 x 128] tile = A(hi+lo) @ Wt(hi+lo)^T ----------------
// smem: Ah/Al [128][72], Wh/Wl [128][72] (both stored row x k-chunk-64, +8 pad)
#define SMSTR 72
#define SM_BYTES (4 * 128 * SMSTR * 2)

__device__ __forceinline__ void ldsm4(uint32_t* r, uint32_t addr) {
    asm volatile("ldmatrix.sync.aligned.m8n8.x4.shared.b16 {%0,%1,%2,%3}, [%4];"
                 : "=r"(r[0]), "=r"(r[1]), "=r"(r[2]), "=r"(r[3]) : "r"(addr));
}
__device__ __forceinline__ void mma16816(float* c, const uint32_t* a, uint32_t b0, uint32_t b1) {
    asm volatile("mma.sync.aligned.m16n8k16.row.col.f32.f16.f16.f32 "
                 "{%0,%1,%2,%3}, {%4,%5,%6,%7}, {%8,%9}, {%0,%1,%2,%3};"
                 : "+f"(c[0]), "+f"(c[1]), "+f"(c[2]), "+f"(c[3])
                 : "r"(a[0]), "r"(a[1]), "r"(a[2]), "r"(a[3]), "r"(b0), "r"(b1));
}

__global__ __launch_bounds__(256, 2) void sage_mma(
    const __half* __restrict__ Whg, const __half* __restrict__ Wlg,
    const float* __restrict__ bias, float* __restrict__ hout,
    __half* __restrict__ selfhi, __half* __restrict__ selflo,   // may be null
    int Ktot)
{
    extern __shared__ __half sm[];
    __half* sAh = sm;
    __half* sAl = sAh + 128 * SMSTR;
    __half* sWh = sAl + 128 * SMSTR;
    __half* sWl = sWh + 128 * SMSTR;

    int tid = threadIdx.x;
    int lane = tid & 31, wid = tid >> 5;
    int warpM = wid & 3, warpN = wid >> 2;       // 4 x 2 warp grid
    int row0 = blockIdx.x * 128;

    float acc[2][8][4];
#pragma unroll
    for (int a = 0; a < 2; a++)
#pragma unroll
        for (int b = 0; b < 8; b++)
#pragma unroll
            for (int c = 0; c < 4; c++) acc[a][b][c] = 0.f;

    // ldmatrix lane address components (same pattern for A and W)
    int frow = (lane & 7) + ((lane >> 3) & 1) * 8;   // row within 16-row frag
    int fcol = (lane >> 4) * 8;                      // k-offset within 16

    uint32_t sAh32 = (uint32_t)__cvta_generic_to_shared(sAh);
    uint32_t sAl32 = (uint32_t)__cvta_generic_to_shared(sAl);
    uint32_t sWh32 = (uint32_t)__cvta_generic_to_shared(sWh);
    uint32_t sWl32 = (uint32_t)__cvta_generic_to_shared(sWl);

    int nch = Ktot >> 6;
    for (int kc = 0; kc < nch; kc++) {
        // ---- stage A (128 rows x 64 k) and W (128 n x 64 k), uint4 = 8 halves ----
        {
            int r = tid >> 3, c = (tid & 7) * 8;
#pragma unroll
            for (int it = 0; it < 4; it++) {
                int rr = r + it * 32;
                size_t go = (size_t)(row0 + rr) * ASTRIDE + kc * 64 + c;
                uint4 vh = make_uint4(0, 0, 0, 0), vl = vh;
                if (row0 + rr < NNODES) {
                    vh = *(const uint4*)&g_Ahi[go];
                    vl = *(const uint4*)&g_Alo[go];
                }
                *(uint4*)&sAh[rr * SMSTR + c] = vh;
                *(uint4*)&sAl[rr * SMSTR + c] = vl;
                size_t wo = (size_t)rr * ASTRIDE + kc * 64 + c;
                *(uint4*)&sWh[rr * SMSTR + c] = *(const uint4*)&Whg[wo];
                *(uint4*)&sWl[rr * SMSTR + c] = *(const uint4*)&Wlg[wo];
            }
        }
        __syncthreads();

#pragma unroll
        for (int k16 = 0; k16 < 4; k16++) {
            int k0 = k16 * 16;
            uint32_t ah[2][4], al[2][4];
#pragma unroll
            for (int mf = 0; mf < 2; mf++) {
                uint32_t off = (uint32_t)(((warpM * 32 + mf * 16 + frow) * SMSTR + k0 + fcol) * 2);
                ldsm4(ah[mf], sAh32 + off);
                ldsm4(al[mf], sAl32 + off);
            }
#pragma unroll
            for (int nf2 = 0; nf2 < 4; nf2++) {
                uint32_t boff = (uint32_t)(((warpN * 64 + nf2 * 16 + frow) * SMSTR + k0 + fcol) * 2);
                uint32_t bh[4], bl[4];
                ldsm4(bh, sWh32 + boff);
                ldsm4(bl, sWl32 + boff);
                // frag nf2*2:   {bh[0], bh[2]};  nf2*2+1: {bh[1], bh[3]}
#pragma unroll
                for (int mf = 0; mf < 2; mf++) {
#pragma unroll
                    for (int h = 0; h < 2; h++) {
                        float* c = acc[mf][nf2 * 2 + h];
                        mma16816(c, ah[mf], bh[h], bh[h + 2]);
                        mma16816(c, ah[mf], bl[h], bl[h + 2]);
                        mma16816(c, al[mf], bh[h], bh[h + 2]);
                    }
                }
            }
        }
        __syncthreads();
    }

    // ---- epilogue: bias + relu, write fp32 h and optional fp16 hi/lo self-half ----
#pragma unroll
    for (int mf = 0; mf < 2; mf++) {
#pragma unroll
        for (int nf = 0; nf < 8; nf++) {
            int cc = warpN * 64 + nf * 8 + (lane & 3) * 2;
            float b0 = bias[cc], b1 = bias[cc + 1];
#pragma unroll
            for (int h = 0; h < 2; h++) {
                int rr = row0 + warpM * 32 + mf * 16 + (lane >> 2) + h * 8;
                if (rr < NNODES) {
                    float v0 = fmaxf(acc[mf][nf][h * 2 + 0] + b0, 0.f);
                    float v1 = fmaxf(acc[mf][nf][h * 2 + 1] + b1, 0.f);
                    *(float2*)&hout[(size_t)rr * 128 + cc] = make_float2(v0, v1);
                    if (selfhi) {
                        __half2 hi, lo;
                        split2(v0, v1, hi, lo);
                        *(__half2*)&selfhi[(size_t)rr * ASTRIDE + 128 + cc] = hi;
                        *(__half2*)&selflo[(size_t)rr * ASTRIDE + 128 + cc] = lo;
                    }
                }
            }
        }
    }
}

// ---------------- pooling: block per graph, batch is sorted ----------------
__device__ __forceinline__ int lower_bound_batch(const int* batch, int key) {
    int lo = 0, hi = NNODES;
    while (lo < hi) {
        int mid = (lo + hi) >> 1;
        if (batch[mid] < key) lo = mid + 1; else hi = mid;
    }
    return lo;
}
__global__ __launch_bounds__(DH) void pool_kernel(const int* __restrict__ batch,
                                                  const float* __restrict__ h) {
    __shared__ int s_start, s_end;
    int g = blockIdx.x;
    if (threadIdx.x == 0) s_start = lower_bound_batch(batch, g);
    if (threadIdx.x == 1) s_end   = lower_bound_batch(batch, g + 1);
    __syncthreads();
    int start = s_start, end = s_end;
    float acc = 0.f;
    int col = threadIdx.x;
#pragma unroll 4
    for (int n = start; n < end; n++)
        acc += h[(size_t)n * DH + col];
    g_pooled[g * DH + col] = acc / (float)max(end - start, 1);
}

// ---------------- final MLP ----------------
__global__ __launch_bounds__(NEMB) void mlp_kernel(
    const float* __restrict__ W1, const float* __restrict__ bl1,
    const float* __restrict__ W2, const float* __restrict__ bl2,
    float* __restrict__ out)
{
    __shared__ float p[DH];
    __shared__ float hid[NEMB];
    int g = blockIdx.x;
    int t = threadIdx.x;
    p[t]      = g_pooled[g * DH + t];
    p[t + 64] = g_pooled[g * DH + 64 + t];
    __syncthreads();
    float s = bl1[t];
#pragma unroll 8
    for (int k = 0; k < DH; k++) s += p[k] * W1[k * NEMB + t];
    hid[t] = fmaxf(s, 0.f);
    __syncthreads();
    float o = bl2[t];
#pragma unroll 8
    for (int j = 0; j < NEMB; j++) o += hid[j] * W2[j * NEMB + t];
    out[g * NEMB + t] = o;
}

// ---------------- launch ----------------
extern "C" void kernel_launch(void* const* d_in, const int* in_sizes, int n_in,
                              void* d_out, int out_size) {
    const float* x     = (const float*)d_in[0];
    const int*   ei    = (const int*)d_in[1];      // int32 (JAX x64 disabled)
    const int*   src   = ei;
    const int*   dst   = ei + NEDGES;
    const int*   batch = (const int*)d_in[2];
    const float *Wl1 = (const float*)d_in[3],  *Wr1 = (const float*)d_in[4],  *b1 = (const float*)d_in[5];
    const float *Wl2 = (const float*)d_in[6],  *Wr2 = (const float*)d_in[7],  *b2 = (const float*)d_in[8];
    const float *Wl3 = (const float*)d_in[9],  *Wr3 = (const float*)d_in[10], *b3 = (const float*)d_in[11];
    const float *W1  = (const float*)d_in[12], *bl1 = (const float*)d_in[13];
    const float *W2  = (const float*)d_in[14], *bl2 = (const float*)d_in[15];

    float* h;    cudaGetSymbolAddress((void**)&h,  g_h);
    __half *Ahi, *Alo, *W1h, *W1l, *W2h, *W2l, *W3h, *W3l;
    cudaGetSymbolAddress((void**)&Ahi, g_Ahi); cudaGetSymbolAddress((void**)&Alo, g_Alo);
    cudaGetSymbolAddress((void**)&W1h, g_W1h); cudaGetSymbolAddress((void**)&W1l, g_W1l);
    cudaGetSymbolAddress((void**)&W2h, g_W2h); cudaGetSymbolAddress((void**)&W2l, g_W2l);
    cudaGetSymbolAddress((void**)&W3h, g_W3h); cudaGetSymbolAddress((void**)&W3l, g_W3l);

    cudaFuncSetAttribute(sage_mma, cudaFuncAttributeMaxDynamicSharedMemorySize, SM_BYTES);

    const int T = 256;
    int warp_blocks = (NNODES * 32 + T - 1) / T;

    // ---- CSR build ----
    zero_deg_kernel<<<(NNODES + T - 1) / T, T>>>();
    hist_kernel<<<(NEDGES + T - 1) / T, T>>>(dst);
    scan_block_kernel<<<NBLK, SCANB>>>();
    scan_part_kernel<<<1, 128>>>();
    scan_add_kernel<<<(NNODES + T - 1) / T, T>>>();
    fill_kernel<<<(NEDGES + T - 1) / T, T>>>(src, dst);

    // ---- operand prep ----
    x2h_kernel<<<(NNODES * (DIN / 2) + T - 1) / T, T>>>(x);
    prep_w<<<(128 * 128 + T - 1) / T, T>>>(Wl1, Wr1, 64,  W1h, W1l);
    prep_w<<<(128 * 256 + T - 1) / T, T>>>(Wl2, Wr2, 128, W2h, W2l);
    prep_w<<<(128 * 256 + T - 1) / T, T>>>(Wl3, Wr3, 128, W3h, W3l);

    // ---- layer 1 (Ktot=128): agg(x) -> A[0:64); self in A[64:128) ----
    agg64_kernel<<<warp_blocks, T>>>(x);
    sage_mma<<<NTILES, 256, SM_BYTES>>>(W1h, W1l, b1, h, Ahi, Alo, 128);

    // ---- layer 2 (Ktot=256): agg(h) -> A[0:128); self (h1) already in A[128:256) ----
    agg128_kernel<<<warp_blocks, T>>>(h);
    sage_mma<<<NTILES, 256, SM_BYTES>>>(W2h, W2l, b2, h, Ahi, Alo, 256);

    // ---- layer 3 ----
    agg128_kernel<<<warp_blocks, T>>>(h);
    sage_mma<<<NTILES, 256, SM_BYTES>>>(W3h, W3l, b3, h, (__half*)nullptr, (__half*)nullptr, 256);

    // ---- pool + MLP ----
    pool_kernel<<<NG, DH>>>(batch, h);
    mlp_kernel<<<NG, NEMB>>>(W1, bl1, W2, bl2, (float*)d_out);
}